// round 11
// baseline (speedup 1.0000x reference)
#include <cuda_runtime.h>
#include <math.h>

// Problem constants
#define BB   8
#define SS   4
#define TT   2048
#define LL   2
#define NH   32
#define NKV  8
#define HD   128
#define DIM  4096
#define NHHD 4096     // NH*HD
#define KVD  1024     // NKV*HD
#define MM   32       // B*S
#define SPLIT 8
#define NCH  32       // attention T-dim chunks
#define NCH2 (NCH+1)  // + 1 fixup slot
#define CHT  (TT/NCH) // 64 tokens per chunk
#define QK_SCALE 0.08838834764831845f  // 1/sqrt(128)

// ---------------- scratch (device globals; no allocations allowed) ----------------
__device__ float g_q[MM * NHHD];            // accumulated then roped+scaled q
__device__ float g_k[MM * KVD];             // accumulated then roped k
__device__ float g_v[MM * KVD];             // accumulated v
__device__ float g_attn[MM * NHHD];
__device__ float g_pl[BB * NH * NCH2 * SS];
__device__ float g_pa[BB * NH * NCH2 * SS * HD];

// ---------------- tf32 / f32x2 helpers ----------------------------------------------
__device__ __forceinline__ unsigned f2tf32(float x) {
    unsigned r;
    asm("cvt.rna.tf32.f32 %0, %1;" : "=r"(r) : "f"(x));
    return r;
}

__device__ __forceinline__ void mma_tf32(float c[4], const unsigned a[4], const unsigned b[2]) {
    asm volatile("mma.sync.aligned.m16n8k8.row.col.f32.tf32.tf32.f32 "
                 "{%0,%1,%2,%3}, {%4,%5,%6,%7}, {%8,%9}, {%0,%1,%2,%3};"
                 : "+f"(c[0]), "+f"(c[1]), "+f"(c[2]), "+f"(c[3])
                 : "r"(a[0]), "r"(a[1]), "r"(a[2]), "r"(a[3]),
                   "r"(b[0]), "r"(b[1]));
}

__device__ __forceinline__ unsigned long long pack2(float lo, float hi) {
    unsigned long long r;
    asm("mov.b64 %0, {%1, %2};" : "=l"(r) : "f"(lo), "f"(hi));
    return r;
}
__device__ __forceinline__ void fma2(unsigned long long& d,
                                     unsigned long long a, unsigned long long b) {
    asm("fma.rn.f32x2 %0, %1, %2, %0;" : "+l"(d) : "l"(a), "l"(b));
}
__device__ __forceinline__ void unpack2(unsigned long long v, float& lo, float& hi) {
    asm("mov.b64 {%0, %1}, %2;" : "=f"(lo), "=f"(hi) : "l"(v));
}

// ---------------- kernel 0: zero accumulation targets -------------------------------
__global__ void __launch_bounds__(256) zero_bufs(float* __restrict__ out)
{
    const int idx = blockIdx.x * 256 + threadIdx.x;
    if (idx < MM * NHHD)  g_q[idx] = 0.f;
    if (idx < MM * KVD) { g_k[idx] = 0.f; g_v[idx] = 0.f; }
    if (idx < MM * DIM)   out[idx] = 0.f;
}

// ---------------- tf32 tensor-core GEMM body, atomic epilogue -----------------------
__device__ __forceinline__ void gemm_body(const float* __restrict__ A,
                                          const float* __restrict__ W,
                                          float* __restrict__ C,
                                          int N, int n0, int k0, int kLen)
{
    __shared__ __align__(16) float As[2][32][36];
    __shared__ __align__(16) float Ws[2][64][68];

    const int tid  = threadIdx.x;
    const int lane = tid & 31;
    const int wid  = tid >> 5;

    auto load_tile = [&](int kt, int buf) {
#pragma unroll
        for (int i = 0; i < 2; i++) {
            int ch = tid + i * 128;
            int row = ch >> 3, kc = (ch & 7) * 4;
            unsigned dst = (unsigned)__cvta_generic_to_shared(&As[buf][row][kc]);
            asm volatile("cp.async.cg.shared.global [%0], [%1], 16;"
                         :: "r"(dst), "l"(A + (long)row * 4096 + kt + kc));
        }
#pragma unroll
        for (int i = 0; i < 4; i++) {
            int ch = tid + i * 128;
            int row = ch >> 3, kc = (ch & 7) * 4;
            unsigned dst = (unsigned)__cvta_generic_to_shared(&Ws[buf][row][kc]);
            asm volatile("cp.async.cg.shared.global [%0], [%1], 16;"
                         :: "r"(dst), "l"(W + (long)(n0 + row) * 4096 + kt + kc));
        }
    };

    float c[2][2][4];
#pragma unroll
    for (int mt = 0; mt < 2; mt++)
#pragma unroll
        for (int nt = 0; nt < 2; nt++)
#pragma unroll
            for (int j = 0; j < 4; j++) c[mt][nt][j] = 0.f;

    load_tile(k0, 0);
    asm volatile("cp.async.commit_group;" ::: "memory");
    asm volatile("cp.async.wait_group 0;" ::: "memory");
    __syncthreads();

    const int r = lane >> 2;
    const int q = lane & 3;

    int buf = 0;
    for (int kt = k0; kt < k0 + kLen; kt += 32) {
        if (kt + 32 < k0 + kLen) load_tile(kt + 32, buf ^ 1);
        asm volatile("cp.async.commit_group;" ::: "memory");

#pragma unroll
        for (int k8 = 0; k8 < 4; k8++) {
            const int kk = k8 * 8 + q;
            unsigned a[2][4], b[2][2];
#pragma unroll
            for (int mt = 0; mt < 2; mt++) {
                a[mt][0] = f2tf32(As[buf][mt * 16 + r][kk]);
                a[mt][1] = f2tf32(As[buf][mt * 16 + r + 8][kk]);
                a[mt][2] = f2tf32(As[buf][mt * 16 + r][kk + 4]);
                a[mt][3] = f2tf32(As[buf][mt * 16 + r + 8][kk + 4]);
            }
#pragma unroll
            for (int nt = 0; nt < 2; nt++) {
                const int col = wid * 16 + nt * 8 + r;
                b[nt][0] = f2tf32(Ws[buf][col][kk]);
                b[nt][1] = f2tf32(Ws[buf][col][kk + 4]);
            }
#pragma unroll
            for (int mt = 0; mt < 2; mt++)
#pragma unroll
                for (int nt = 0; nt < 2; nt++)
                    mma_tf32(c[mt][nt], a[mt], b[nt]);
        }

        asm volatile("cp.async.wait_group 0;" ::: "memory");
        __syncthreads();
        buf ^= 1;
    }

#pragma unroll
    for (int mt = 0; mt < 2; mt++)
#pragma unroll
        for (int nt = 0; nt < 2; nt++) {
            const int row = mt * 16 + r;
            const int col = n0 + wid * 16 + nt * 8 + q * 2;
            atomicAdd(&C[(long)row * N + col],           c[mt][nt][0]);
            atomicAdd(&C[(long)row * N + col + 1],       c[mt][nt][1]);
            atomicAdd(&C[(long)(row + 8) * N + col],     c[mt][nt][2]);
            atomicAdd(&C[(long)(row + 8) * N + col + 1], c[mt][nt][3]);
        }
}

// ---------------- kernel 1: fused QKV projection ------------------------------------
__global__ void __launch_bounds__(128) qkv_gemm(const float* __restrict__ x,
                                                const float* __restrict__ wq,
                                                const float* __restrict__ wk,
                                                const float* __restrict__ wv)
{
    const int bx = blockIdx.x;
    const int sp = blockIdx.y;
    const int k0 = sp * (4096 / SPLIT);
    const int kl = 4096 / SPLIT;
    if (bx < 64) {
        gemm_body(x, wq, g_q, NHHD, bx * 64, k0, kl);
    } else if (bx < 80) {
        gemm_body(x, wk, g_k, KVD, (bx - 64) * 64, k0, kl);
    } else {
        gemm_body(x, wv, g_v, KVD, (bx - 80) * 64, k0, kl);
    }
}

// ---------------- kernel 2: in-place RoPE (+ q scaling) -----------------------------
__global__ void __launch_bounds__(256) rope_kernel(const float* __restrict__ angles)
{
    const int idx = blockIdx.x * 256 + threadIdx.x;
    const int QP = MM * NH * 64;
    const int KP = MM * NKV * 64;
    if (idx < QP) {
        int m = idx >> 11;
        int j = idx & 63;
        int off = m * NHHD + ((idx >> 6) & 31) * HD + 2 * j;
        float xr = g_q[off], xi = g_q[off + 1];
        float a = angles[m * 64 + j];
        float c, sn; sincosf(a, &sn, &c);
        g_q[off]     = (xr * c - xi * sn) * QK_SCALE;
        g_q[off + 1] = (xr * sn + xi * c) * QK_SCALE;
    } else if (idx < QP + KP) {
        int p = idx - QP;
        int m = p >> 9;
        int j = p & 63;
        int off = m * KVD + ((p >> 6) & 7) * HD + 2 * j;
        float xr = g_k[off], xi = g_k[off + 1];
        float a = angles[m * 64 + j];
        float c, sn; sincosf(a, &sn, &c);
        g_k[off]     = xr * c - xi * sn;
        g_k[off + 1] = xr * sn + xi * c;
    }
}

// ---------------- kernel 3: warp-streaming attention, lean hot loop -----------------
// One warp per (b, h, 64-token chunk). PURE cache streaming: no override state
// at all (fixup lives in its own kernel writing partial slot NCH). Forced to
// <=64 regs -> 8 blocks/SM (32 warps).
__global__ void __launch_bounds__(128, 8) attn_warp(const float* __restrict__ cache_k,
                                                    const float* __restrict__ cache_v,
                                                    const float* __restrict__ mask,
                                                    const int* __restrict__ layer_idx)
{
    const int wg   = blockIdx.x * 4 + (threadIdx.x >> 5);  // 0..8191
    const int lane = threadIdx.x & 31;
    const int bh = wg >> 5;               // 0..255
    const int ch = wg & 31;               // 0..31
    const int b  = bh >> 5;
    const int h  = bh & 31;
    const int li = layer_idx[0];
    const int cls = lane & 3;             // lane class -> owns s = cls

    float q[4][4];
#pragma unroll
    for (int s = 0; s < 4; s++) {
        float4 t = *(const float4*)(g_q + (long)(b * SS + s) * NHHD + h * HD + lane * 4);
        q[s][0] = t.x; q[s][1] = t.y; q[s][2] = t.z; q[s][3] = t.w;
    }

    unsigned long long accp[4][2];
#pragma unroll
    for (int s = 0; s < 4; s++) { accp[s][0] = 0ull; accp[s][1] = 0ull; }
    float lcur = 0.f;

    const long base = (long)b * TT * LL * NHHD + (long)li * NHHD + (long)h * HD;
    const float* mrow = mask + (long)cls * TT;
    const int t_lo = ch * CHT;

    auto finish_token = [&](float x, const float4& v4, int t) {
        float p = __expf(x + mrow[t]);
        lcur += p;
        unsigned long long v01 = pack2(v4.x, v4.y);
        unsigned long long v23 = pack2(v4.z, v4.w);
#pragma unroll
        for (int s = 0; s < 4; s++) {
            float ps = __shfl_sync(0xffffffffu, p, s);
            unsigned long long pp = pack2(ps, ps);
            fma2(accp[s][0], pp, v01);
            fma2(accp[s][1], pp, v23);
        }
    };

    const float* kptr = cache_k + base + lane * 4 + (long)t_lo * LL * NHHD;
    const float* vptr = cache_v + base + lane * 4 + (long)t_lo * LL * NHHD;
    for (int t0 = t_lo; t0 < t_lo + CHT; t0 += 2) {
        float4 k4a = *(const float4*)kptr;
        float4 v4a = *(const float4*)vptr;
        float4 k4b = *(const float4*)(kptr + LL * NHHD);
        float4 v4b = *(const float4*)(vptr + LL * NHHD);
        kptr += 2 * LL * NHHD;
        vptr += 2 * LL * NHHD;

        float dot[2][4];
#pragma unroll
        for (int s = 0; s < 4; s++) {
            float a0 = q[s][0] * k4a.x;
            a0 = fmaf(q[s][1], k4a.y, a0);
            a0 = fmaf(q[s][2], k4a.z, a0);
            a0 = fmaf(q[s][3], k4a.w, a0);
            dot[0][s] = a0;
            float a1 = q[s][0] * k4b.x;
            a1 = fmaf(q[s][1], k4b.y, a1);
            a1 = fmaf(q[s][2], k4b.z, a1);
            a1 = fmaf(q[s][3], k4b.w, a1);
            dot[1][s] = a1;
        }

#pragma unroll
        for (int o = 1; o <= 2; o <<= 1)
#pragma unroll
            for (int i = 0; i < 2; i++)
#pragma unroll
                for (int s = 0; s < 4; s++)
                    dot[i][s] += __shfl_xor_sync(0xffffffffu, dot[i][s], o);

        float xa = (cls == 0) ? dot[0][0] : (cls == 1) ? dot[0][1]
                 : (cls == 2) ? dot[0][2] : dot[0][3];
        float xb = (cls == 0) ? dot[1][0] : (cls == 1) ? dot[1][1]
                 : (cls == 2) ? dot[1][2] : dot[1][3];
#pragma unroll
        for (int o = 4; o <= 16; o <<= 1) {
            xa += __shfl_xor_sync(0xffffffffu, xa, o);
            xb += __shfl_xor_sync(0xffffffffu, xb, o);
        }

        finish_token(xa, v4a, t0);
        finish_token(xb, v4b, t0 + 1);
    }

    const long pbase = ((long)(bh * NCH2 + ch)) * SS;
#pragma unroll
    for (int s = 0; s < 4; s++) {
        float4 o;
        unpack2(accp[s][0], o.x, o.y);
        unpack2(accp[s][1], o.z, o.w);
        *(float4*)(g_pa + (pbase + s) * HD + lane * 4) = o;
    }
    if (lane < 4) g_pl[pbase + lane] = lcur;
}

// ---------------- kernel 3f: override fixup into partial slot NCH -------------------
// One warp per (b, h): subtract the bit-identical cache contribution of rows
// [sp, sp+SS), add the new-token contribution. Same FMA/shuffle sequence as the
// hot kernel's per-token chain -> exact cancellation. Valid because no-max
// softmax partials are plain sums of exp terms.
__global__ void __launch_bounds__(128) attn_fixup(const float* __restrict__ cache_k,
                                                  const float* __restrict__ cache_v,
                                                  const float* __restrict__ mask,
                                                  const int* __restrict__ start_pos,
                                                  const int* __restrict__ layer_idx)
{
    const int bh   = blockIdx.x * 4 + (threadIdx.x >> 5);  // 0..255
    const int lane = threadIdx.x & 31;
    const int b  = bh >> 5;
    const int h  = bh & 31;
    const int li = layer_idx[0];
    const int sp = start_pos[b];
    const int kvh = h >> 2;
    const int cls = lane & 3;

    float q[4][4];
#pragma unroll
    for (int s = 0; s < 4; s++) {
        float4 t = *(const float4*)(g_q + (long)(b * SS + s) * NHHD + h * HD + lane * 4);
        q[s][0] = t.x; q[s][1] = t.y; q[s][2] = t.z; q[s][3] = t.w;
    }

    unsigned long long accp[4][2];
#pragma unroll
    for (int s = 0; s < 4; s++) { accp[s][0] = 0ull; accp[s][1] = 0ull; }
    float lcur = 0.f;

    const long base = (long)b * TT * LL * NHHD + (long)li * NHHD + (long)h * HD;
    const float* mrow = mask + (long)cls * TT;

    auto do_token = [&](const float4& k4, const float4& v4, int t, float sign) {
        float dot[4];
#pragma unroll
        for (int s = 0; s < 4; s++) {
            float a = q[s][0] * k4.x;
            a = fmaf(q[s][1], k4.y, a);
            a = fmaf(q[s][2], k4.z, a);
            a = fmaf(q[s][3], k4.w, a);
            dot[s] = a;
        }
#pragma unroll
        for (int o = 1; o <= 2; o <<= 1)
#pragma unroll
            for (int s = 0; s < 4; s++)
                dot[s] += __shfl_xor_sync(0xffffffffu, dot[s], o);
        float x = (cls == 0) ? dot[0] : (cls == 1) ? dot[1]
                : (cls == 2) ? dot[2] : dot[3];
#pragma unroll
        for (int o = 4; o <= 16; o <<= 1)
            x += __shfl_xor_sync(0xffffffffu, x, o);

        float p = sign * __expf(x + mrow[t]);
        lcur += p;
        unsigned long long v01 = pack2(v4.x, v4.y);
        unsigned long long v23 = pack2(v4.z, v4.w);
#pragma unroll
        for (int s = 0; s < 4; s++) {
            float ps = __shfl_sync(0xffffffffu, p, s);
            unsigned long long pp = pack2(ps, ps);
            fma2(accp[s][0], pp, v01);
            fma2(accp[s][1], pp, v23);
        }
    };

#pragma unroll
    for (int i = 0; i < SS; i++) {
        int t = sp + i;
        float4 kc = *(const float4*)(cache_k + base + (long)t * LL * NHHD + lane * 4);
        float4 vc = *(const float4*)(cache_v + base + (long)t * LL * NHHD + lane * 4);
        do_token(kc, vc, t, -1.f);
        long noff = ((long)((b * SS + i) * NKV + kvh)) * HD + lane * 4;
        float4 kn = *(const float4*)(g_k + noff);
        float4 vn = *(const float4*)(g_v + noff);
        do_token(kn, vn, t, 1.f);
    }

    const long pbase = ((long)(bh * NCH2 + NCH)) * SS;   // fixup slot
#pragma unroll
    for (int s = 0; s < 4; s++) {
        float4 o;
        unpack2(accp[s][0], o.x, o.y);
        unpack2(accp[s][1], o.z, o.w);
        *(float4*)(g_pa + (pbase + s) * HD + lane * 4) = o;
    }
    if (lane < 4) g_pl[pbase + lane] = lcur;
}

// ---------------- kernel 3b: combine split-T partials (+ fixup slot) ----------------
__global__ void __launch_bounds__(256) attn_combine()
{
    const int idx = blockIdx.x * 256 + threadIdx.x;
    const int bh = idx >> 9;
    const int s  = (idx >> 7) & 3;
    const int d  = idx & 127;
    const int b  = bh >> 5;
    const int h  = bh & 31;

    float num = 0.f, den = 0.f;
#pragma unroll
    for (int c = 0; c < NCH2; c++) {
        long pb = ((long)(bh * NCH2 + c)) * SS + s;
        num += g_pa[pb * HD + d];
        den += g_pl[pb];
    }
    g_attn[(long)(b * SS + s) * NHHD + h * HD + d] = num / den;
}

// ---------------- kernel 4: output projection (accumulates into out) ----------------
__global__ void __launch_bounds__(128) out_gemm(const float* __restrict__ wo,
                                                float* __restrict__ out)
{
    gemm_body(g_attn, wo, out, DIM,
              blockIdx.x * 64, blockIdx.y * (4096 / SPLIT), 4096 / SPLIT);
}

// ---------------- launch -------------------------------------------------------------
extern "C" void kernel_launch(void* const* d_in, const int* in_sizes, int n_in,
                              void* d_out, int out_size)
{
    const float* x         = (const float*)d_in[0];
    const int*   start_pos = (const int*)  d_in[1];
    const float* angles    = (const float*)d_in[2];
    const float* cache_k   = (const float*)d_in[3];
    const float* cache_v   = (const float*)d_in[4];
    const float* mask      = (const float*)d_in[5];
    const float* wq        = (const float*)d_in[6];
    const float* wk        = (const float*)d_in[7];
    const float* wv        = (const float*)d_in[8];
    const float* wo        = (const float*)d_in[9];
    const int*   layer_idx = (const int*)  d_in[10];
    float* out = (float*)d_out;

    zero_bufs<<<512, 256>>>(out);                                  // launch 1
    qkv_gemm<<<dim3(96, SPLIT), 128>>>(x, wq, wk, wv);             // launch 2
    rope_kernel<<<320, 256>>>(angles);                             // launch 3
    attn_warp<<<2048, 128>>>(cache_k, cache_v, mask, layer_idx);   // launch 4 (profiled)
    attn_fixup<<<64, 128>>>(cache_k, cache_v, mask,                // launch 5
                            start_pos, layer_idx);
    attn_combine<<<512, 256>>>();                                  // launch 6
    out_gemm<<<dim3(64, SPLIT), 128>>>(wo, out);                   // launch 7
}

// round 12
// speedup vs baseline: 1.1191x; 1.1191x over previous
#include <cuda_runtime.h>
#include <math.h>

// Problem constants
#define BB   8
#define SS   4
#define TT   2048
#define LL   2
#define NH   32
#define NKV  8
#define HD   128
#define DIM  4096
#define NHHD 4096     // NH*HD
#define KVD  1024     // NKV*HD
#define MM   32       // B*S
#define SPLIT 8
#define NCH  32       // attention T-dim chunks
#define CHT  (TT/NCH) // 64 tokens per chunk
#define QK_SCALE 0.08838834764831845f  // 1/sqrt(128)

// ---------------- scratch (device globals; no allocations allowed) ----------------
__device__ float g_q[MM * NHHD];
__device__ float g_k[MM * KVD];
__device__ float g_v[MM * KVD];
__device__ float g_attn[MM * NHHD];
__device__ float g_pl[BB * NH * NCH * SS];
__device__ float g_pa[BB * NH * NCH * SS * HD];

// ---------------- tf32 / f32x2 helpers ----------------------------------------------
__device__ __forceinline__ unsigned f2tf32(float x) {
    unsigned r;
    asm("cvt.rna.tf32.f32 %0, %1;" : "=r"(r) : "f"(x));
    return r;
}

__device__ __forceinline__ void mma_tf32(float c[4], const unsigned a[4], const unsigned b[2]) {
    asm volatile("mma.sync.aligned.m16n8k8.row.col.f32.tf32.tf32.f32 "
                 "{%0,%1,%2,%3}, {%4,%5,%6,%7}, {%8,%9}, {%0,%1,%2,%3};"
                 : "+f"(c[0]), "+f"(c[1]), "+f"(c[2]), "+f"(c[3])
                 : "r"(a[0]), "r"(a[1]), "r"(a[2]), "r"(a[3]),
                   "r"(b[0]), "r"(b[1]));
}

__device__ __forceinline__ unsigned long long pack2(float lo, float hi) {
    unsigned long long r;
    asm("mov.b64 %0, {%1, %2};" : "=l"(r) : "f"(lo), "f"(hi));
    return r;
}
__device__ __forceinline__ void fma2(unsigned long long& d,
                                     unsigned long long a, unsigned long long b) {
    asm("fma.rn.f32x2 %0, %1, %2, %0;" : "+l"(d) : "l"(a), "l"(b));
}
__device__ __forceinline__ void unpack2(unsigned long long v, float& lo, float& hi) {
    asm("mov.b64 {%0, %1}, %2;" : "=f"(lo), "=f"(hi) : "l"(v));
}

// ---------------- kernels 0a/0b/0c: zero accumulation targets ------------------------
// Split so qkv_gemm is the profiled 4th launch.
__global__ void __launch_bounds__(256) zero_q()
{
    const int idx = blockIdx.x * 256 + threadIdx.x;
    g_q[idx] = 0.f;
}
__global__ void __launch_bounds__(256) zero_kv()
{
    const int idx = blockIdx.x * 256 + threadIdx.x;
    g_k[idx] = 0.f; g_v[idx] = 0.f;
}
__global__ void __launch_bounds__(256) zero_out(float* __restrict__ out)
{
    const int idx = blockIdx.x * 256 + threadIdx.x;
    out[idx] = 0.f;
}

// ---------------- tf32 GEMM body: 3-stage cp.async pipeline, atomic epilogue --------
// C[32 x N] += A[32 x 4096] * W[N x 4096]^T on the k0..k0+kLen slice.
// Stage s holds one 32-wide K tile; wait_group 1 keeps a load in flight under
// the MMA of the current tile. Smem stride 36 (32 data + 4 pad): cp.async dst
// 16B-aligned (36*4=144B rows), scalar fragment LDS conflict-free
// (36 mod 32 = 4 -> bank = 4*row + kk covers all 32 banks per warp).
__device__ __forceinline__ void gemm_body(const float* __restrict__ A,
                                          const float* __restrict__ W,
                                          float* __restrict__ C,
                                          int N, int n0, int k0, int kLen)
{
    __shared__ __align__(16) float As[3][32][36];
    __shared__ __align__(16) float Ws[3][64][36];

    const int tid  = threadIdx.x;
    const int lane = tid & 31;
    const int wid  = tid >> 5;

    auto load_tile = [&](int kt, int buf) {
#pragma unroll
        for (int i = 0; i < 2; i++) {
            int ch = tid + i * 128;
            int row = ch >> 3, kc = (ch & 7) * 4;
            unsigned dst = (unsigned)__cvta_generic_to_shared(&As[buf][row][kc]);
            asm volatile("cp.async.cg.shared.global [%0], [%1], 16;"
                         :: "r"(dst), "l"(A + (long)row * 4096 + kt + kc));
        }
#pragma unroll
        for (int i = 0; i < 4; i++) {
            int ch = tid + i * 128;
            int row = ch >> 3, kc = (ch & 7) * 4;
            unsigned dst = (unsigned)__cvta_generic_to_shared(&Ws[buf][row][kc]);
            asm volatile("cp.async.cg.shared.global [%0], [%1], 16;"
                         :: "r"(dst), "l"(W + (long)(n0 + row) * 4096 + kt + kc));
        }
    };

    float c[2][2][4];
#pragma unroll
    for (int mt = 0; mt < 2; mt++)
#pragma unroll
        for (int nt = 0; nt < 2; nt++)
#pragma unroll
            for (int j = 0; j < 4; j++) c[mt][nt][j] = 0.f;

    const int nIter = kLen / 32;

    // prologue: stages 0 and 1 in flight
    load_tile(k0, 0);
    asm volatile("cp.async.commit_group;" ::: "memory");
    load_tile(k0 + 32, 1);
    asm volatile("cp.async.commit_group;" ::: "memory");
    asm volatile("cp.async.wait_group 1;" ::: "memory");   // stage 0 ready
    __syncthreads();

    const int r = lane >> 2;
    const int q = lane & 3;

    for (int it = 0; it < nIter; it++) {
        const int buf = it % 3;

        // prefetch stage it+2 (its buffer was last read at iter it-1; the
        // trailing __syncthreads of that iteration protects the overwrite)
        if (it + 2 < nIter) load_tile(k0 + (it + 2) * 32, (it + 2) % 3);
        asm volatile("cp.async.commit_group;" ::: "memory");

        // compute on stage it
#pragma unroll
        for (int k8 = 0; k8 < 4; k8++) {
            const int kk = k8 * 8 + q;
            unsigned a[2][4], b[2][2];
#pragma unroll
            for (int mt = 0; mt < 2; mt++) {
                a[mt][0] = f2tf32(As[buf][mt * 16 + r][kk]);
                a[mt][1] = f2tf32(As[buf][mt * 16 + r + 8][kk]);
                a[mt][2] = f2tf32(As[buf][mt * 16 + r][kk + 4]);
                a[mt][3] = f2tf32(As[buf][mt * 16 + r + 8][kk + 4]);
            }
#pragma unroll
            for (int nt = 0; nt < 2; nt++) {
                const int col = wid * 16 + nt * 8 + r;
                b[nt][0] = f2tf32(Ws[buf][col][kk]);
                b[nt][1] = f2tf32(Ws[buf][col][kk + 4]);
            }
#pragma unroll
            for (int mt = 0; mt < 2; mt++)
#pragma unroll
                for (int nt = 0; nt < 2; nt++)
                    mma_tf32(c[mt][nt], a[mt], b[nt]);
        }

        // wait until only the just-committed group is outstanding -> stage it+1 ready
        asm volatile("cp.async.wait_group 1;" ::: "memory");
        __syncthreads();
    }

    // split-K accumulation straight into C via REDG
#pragma unroll
    for (int mt = 0; mt < 2; mt++)
#pragma unroll
        for (int nt = 0; nt < 2; nt++) {
            const int row = mt * 16 + r;
            const int col = n0 + wid * 16 + nt * 8 + q * 2;
            atomicAdd(&C[(long)row * N + col],           c[mt][nt][0]);
            atomicAdd(&C[(long)row * N + col + 1],       c[mt][nt][1]);
            atomicAdd(&C[(long)(row + 8) * N + col],     c[mt][nt][2]);
            atomicAdd(&C[(long)(row + 8) * N + col + 1], c[mt][nt][3]);
        }
}

// ---------------- kernel 1: fused QKV projection ------------------------------------
__global__ void __launch_bounds__(128) qkv_gemm(const float* __restrict__ x,
                                                const float* __restrict__ wq,
                                                const float* __restrict__ wk,
                                                const float* __restrict__ wv)
{
    const int bx = blockIdx.x;
    const int sp = blockIdx.y;
    const int k0 = sp * (4096 / SPLIT);
    const int kl = 4096 / SPLIT;
    if (bx < 64) {
        gemm_body(x, wq, g_q, NHHD, bx * 64, k0, kl);
    } else if (bx < 80) {
        gemm_body(x, wk, g_k, KVD, (bx - 64) * 64, k0, kl);
    } else {
        gemm_body(x, wv, g_v, KVD, (bx - 80) * 64, k0, kl);
    }
}

// ---------------- kernel 2: in-place RoPE (+ q scaling) -----------------------------
__global__ void __launch_bounds__(256) rope_kernel(const float* __restrict__ angles)
{
    const int idx = blockIdx.x * 256 + threadIdx.x;
    const int QP = MM * NH * 64;
    const int KP = MM * NKV * 64;
    if (idx < QP) {
        int m = idx >> 11;
        int j = idx & 63;
        int off = m * NHHD + ((idx >> 6) & 31) * HD + 2 * j;
        float xr = g_q[off], xi = g_q[off + 1];
        float a = angles[m * 64 + j];
        float c, sn; sincosf(a, &sn, &c);
        g_q[off]     = (xr * c - xi * sn) * QK_SCALE;
        g_q[off + 1] = (xr * sn + xi * c) * QK_SCALE;
    } else if (idx < QP + KP) {
        int p = idx - QP;
        int m = p >> 9;
        int j = p & 63;
        int off = m * KVD + ((p >> 6) & 7) * HD + 2 * j;
        float xr = g_k[off], xi = g_k[off + 1];
        float a = angles[m * 64 + j];
        float c, sn; sincosf(a, &sn, &c);
        g_k[off]     = xr * c - xi * sn;
        g_k[off + 1] = xr * sn + xi * c;
    }
}

// ---------------- kernel 3: warp-streaming attention (R10 form, frozen) -------------
__global__ void __launch_bounds__(128, 7) attn_warp(const float* __restrict__ cache_k,
                                                    const float* __restrict__ cache_v,
                                                    const float* __restrict__ mask,
                                                    const int* __restrict__ start_pos,
                                                    const int* __restrict__ layer_idx)
{
    const int wg   = blockIdx.x * 4 + (threadIdx.x >> 5);  // 0..8191
    const int lane = threadIdx.x & 31;
    const int bh = wg >> 5;
    const int ch = wg & 31;
    const int b  = bh >> 5;
    const int h  = bh & 31;
    const int li = layer_idx[0];
    const int sp = start_pos[b];
    const int cls = lane & 3;

    float q[4][4];
#pragma unroll
    for (int s = 0; s < 4; s++) {
        float4 t = *(const float4*)(g_q + (long)(b * SS + s) * NHHD + h * HD + lane * 4);
        q[s][0] = t.x; q[s][1] = t.y; q[s][2] = t.z; q[s][3] = t.w;
    }

    unsigned long long accp[4][2];
#pragma unroll
    for (int s = 0; s < 4; s++) { accp[s][0] = 0ull; accp[s][1] = 0ull; }
    float lcur = 0.f;

    const long base = (long)b * TT * LL * NHHD + (long)li * NHHD + (long)h * HD;
    const float* mrow = mask + (long)cls * TT;
    const int t_lo = ch * CHT;

    auto finish_token = [&](float x, const float4& v4, int t, float sign) {
        float p = sign * __expf(x + mrow[t]);
        lcur += p;
        unsigned long long v01 = pack2(v4.x, v4.y);
        unsigned long long v23 = pack2(v4.z, v4.w);
#pragma unroll
        for (int s = 0; s < 4; s++) {
            float ps = __shfl_sync(0xffffffffu, p, s);
            unsigned long long pp = pack2(ps, ps);
            fma2(accp[s][0], pp, v01);
            fma2(accp[s][1], pp, v23);
        }
    };

    auto do_token = [&](const float4& k4, const float4& v4, int t, float sign) {
        float dot[4];
#pragma unroll
        for (int s = 0; s < 4; s++) {
            float a = q[s][0] * k4.x;
            a = fmaf(q[s][1], k4.y, a);
            a = fmaf(q[s][2], k4.z, a);
            a = fmaf(q[s][3], k4.w, a);
            dot[s] = a;
        }
#pragma unroll
        for (int o = 1; o <= 2; o <<= 1)
#pragma unroll
            for (int s = 0; s < 4; s++)
                dot[s] += __shfl_xor_sync(0xffffffffu, dot[s], o);
        float x = (cls == 0) ? dot[0] : (cls == 1) ? dot[1]
                : (cls == 2) ? dot[2] : dot[3];
        x += __shfl_xor_sync(0xffffffffu, x, 4);
        x += __shfl_xor_sync(0xffffffffu, x, 8);
        x += __shfl_xor_sync(0xffffffffu, x, 16);
        finish_token(x, v4, t, sign);
    };

    const float* kptr = cache_k + base + lane * 4 + (long)t_lo * LL * NHHD;
    const float* vptr = cache_v + base + lane * 4 + (long)t_lo * LL * NHHD;
    for (int t0 = t_lo; t0 < t_lo + CHT; t0 += 2) {
        float4 k4a = *(const float4*)kptr;
        float4 v4a = *(const float4*)vptr;
        float4 k4b = *(const float4*)(kptr + LL * NHHD);
        float4 v4b = *(const float4*)(vptr + LL * NHHD);
        kptr += 2 * LL * NHHD;
        vptr += 2 * LL * NHHD;

        float dot[2][4];
#pragma unroll
        for (int s = 0; s < 4; s++) {
            float a0 = q[s][0] * k4a.x;
            a0 = fmaf(q[s][1], k4a.y, a0);
            a0 = fmaf(q[s][2], k4a.z, a0);
            a0 = fmaf(q[s][3], k4a.w, a0);
            dot[0][s] = a0;
            float a1 = q[s][0] * k4b.x;
            a1 = fmaf(q[s][1], k4b.y, a1);
            a1 = fmaf(q[s][2], k4b.z, a1);
            a1 = fmaf(q[s][3], k4b.w, a1);
            dot[1][s] = a1;
        }

#pragma unroll
        for (int o = 1; o <= 2; o <<= 1)
#pragma unroll
            for (int i = 0; i < 2; i++)
#pragma unroll
                for (int s = 0; s < 4; s++)
                    dot[i][s] += __shfl_xor_sync(0xffffffffu, dot[i][s], o);

        float xa = (cls == 0) ? dot[0][0] : (cls == 1) ? dot[0][1]
                 : (cls == 2) ? dot[0][2] : dot[0][3];
        float xb = (cls == 0) ? dot[1][0] : (cls == 1) ? dot[1][1]
                 : (cls == 2) ? dot[1][2] : dot[1][3];
#pragma unroll
        for (int o = 4; o <= 16; o <<= 1) {
            xa += __shfl_xor_sync(0xffffffffu, xa, o);
            xb += __shfl_xor_sync(0xffffffffu, xb, o);
        }

        finish_token(xa, v4a, t0,     1.f);
        finish_token(xb, v4b, t0 + 1, 1.f);
    }

    // fixup: overridden rows [sp, sp+SS) within this chunk
    {
        int lo = t_lo > sp ? t_lo : sp;
        int hi_ = t_lo + CHT < sp + SS ? t_lo + CHT : sp + SS;
        const int kvh = h >> 2;
        for (int t = lo; t < hi_; ++t) {
            float4 kc = *(const float4*)(cache_k + base + (long)t * LL * NHHD + lane * 4);
            float4 vc = *(const float4*)(cache_v + base + (long)t * LL * NHHD + lane * 4);
            do_token(kc, vc, t, -1.f);
            long noff = ((long)((b * SS + (t - sp)) * NKV + kvh)) * HD + lane * 4;
            float4 kn = *(const float4*)(g_k + noff);
            float4 vn = *(const float4*)(g_v + noff);
            do_token(kn, vn, t, 1.f);
        }
    }

    const long pbase = ((long)(bh * NCH + ch)) * SS;
#pragma unroll
    for (int s = 0; s < 4; s++) {
        float4 o;
        unpack2(accp[s][0], o.x, o.y);
        unpack2(accp[s][1], o.z, o.w);
        *(float4*)(g_pa + (pbase + s) * HD + lane * 4) = o;
    }
    if (lane < 4) g_pl[pbase + lane] = lcur;
}

// ---------------- kernel 3b: combine split-T partials -------------------------------
__global__ void __launch_bounds__(256) attn_combine()
{
    const int idx = blockIdx.x * 256 + threadIdx.x;
    const int bh = idx >> 9;
    const int s  = (idx >> 7) & 3;
    const int d  = idx & 127;
    const int b  = bh >> 5;
    const int h  = bh & 31;

    float num = 0.f, den = 0.f;
#pragma unroll
    for (int c = 0; c < NCH; c++) {
        long pb = ((long)(bh * NCH + c)) * SS + s;
        num += g_pa[pb * HD + d];
        den += g_pl[pb];
    }
    g_attn[(long)(b * SS + s) * NHHD + h * HD + d] = num / den;
}

// ---------------- kernel 4: output projection (accumulates into out) ----------------
__global__ void __launch_bounds__(128) out_gemm(const float* __restrict__ wo,
                                                float* __restrict__ out)
{
    gemm_body(g_attn, wo, out, DIM,
              blockIdx.x * 64, blockIdx.y * (4096 / SPLIT), 4096 / SPLIT);
}

// ---------------- launch -------------------------------------------------------------
extern "C" void kernel_launch(void* const* d_in, const int* in_sizes, int n_in,
                              void* d_out, int out_size)
{
    const float* x         = (const float*)d_in[0];
    const int*   start_pos = (const int*)  d_in[1];
    const float* angles    = (const float*)d_in[2];
    const float* cache_k   = (const float*)d_in[3];
    const float* cache_v   = (const float*)d_in[4];
    const float* mask      = (const float*)d_in[5];
    const float* wq        = (const float*)d_in[6];
    const float* wk        = (const float*)d_in[7];
    const float* wv        = (const float*)d_in[8];
    const float* wo        = (const float*)d_in[9];
    const int*   layer_idx = (const int*)  d_in[10];
    float* out = (float*)d_out;

    zero_q<<<512, 256>>>();                                        // launch 1
    zero_kv<<<128, 256>>>();                                       // launch 2
    zero_out<<<512, 256>>>(out);                                   // launch 3
    qkv_gemm<<<dim3(96, SPLIT), 128>>>(x, wq, wk, wv);             // launch 4 (profiled)
    rope_kernel<<<320, 256>>>(angles);                             // launch 5
    attn_warp<<<2048, 128>>>(cache_k, cache_v, mask,               // launch 6
                             start_pos, layer_idx);
    attn_combine<<<512, 256>>>();                                  // launch 7
    out_gemm<<<dim3(64, SPLIT), 128>>>(wo, out);                   // launch 8
}

// round 13
// speedup vs baseline: 1.1260x; 1.0061x over previous
#include <cuda_runtime.h>
#include <math.h>

// Problem constants
#define BB   8
#define SS   4
#define TT   2048
#define LL   2
#define NH   32
#define NKV  8
#define HD   128
#define DIM  4096
#define NHHD 4096     // NH*HD
#define KVD  1024     // NKV*HD
#define MM   32       // B*S
#define SPLIT 16
#define NCH  32       // attention T-dim chunks
#define CHT  (TT/NCH) // 64 tokens per chunk
#define QK_SCALE 0.08838834764831845f  // 1/sqrt(128)

// ---------------- scratch (device globals; no allocations allowed) ----------------
__device__ float g_q[MM * NHHD];
__device__ float g_k[MM * KVD];
__device__ float g_v[MM * KVD];
__device__ float g_attn[MM * NHHD];
__device__ float g_pl[BB * NH * NCH * SS];
__device__ float g_pa[BB * NH * NCH * SS * HD];

// ---------------- tf32 / f32x2 helpers ----------------------------------------------
__device__ __forceinline__ unsigned f2tf32(float x) {
    unsigned r;
    asm("cvt.rna.tf32.f32 %0, %1;" : "=r"(r) : "f"(x));
    return r;
}

__device__ __forceinline__ void mma_tf32(float c[4], const unsigned a[4], const unsigned b[2]) {
    asm volatile("mma.sync.aligned.m16n8k8.row.col.f32.tf32.tf32.f32 "
                 "{%0,%1,%2,%3}, {%4,%5,%6,%7}, {%8,%9}, {%0,%1,%2,%3};"
                 : "+f"(c[0]), "+f"(c[1]), "+f"(c[2]), "+f"(c[3])
                 : "r"(a[0]), "r"(a[1]), "r"(a[2]), "r"(a[3]),
                   "r"(b[0]), "r"(b[1]));
}

__device__ __forceinline__ unsigned long long pack2(float lo, float hi) {
    unsigned long long r;
    asm("mov.b64 %0, {%1, %2};" : "=l"(r) : "f"(lo), "f"(hi));
    return r;
}
__device__ __forceinline__ void fma2(unsigned long long& d,
                                     unsigned long long a, unsigned long long b) {
    asm("fma.rn.f32x2 %0, %1, %2, %0;" : "+l"(d) : "l"(a), "l"(b));
}
__device__ __forceinline__ void unpack2(unsigned long long v, float& lo, float& hi) {
    asm("mov.b64 {%0, %1}, %2;" : "=f"(lo), "=f"(hi) : "l"(v));
}

// ---------------- kernels 0a/0b/0c: zero accumulation targets ------------------------
__global__ void __launch_bounds__(256) zero_q()
{
    const int idx = blockIdx.x * 256 + threadIdx.x;
    g_q[idx] = 0.f;
}
__global__ void __launch_bounds__(256) zero_kv()
{
    const int idx = blockIdx.x * 256 + threadIdx.x;
    g_k[idx] = 0.f; g_v[idx] = 0.f;
}
__global__ void __launch_bounds__(256) zero_out(float* __restrict__ out)
{
    const int idx = blockIdx.x * 256 + threadIdx.x;
    out[idx] = 0.f;
}

// ---------------- tf32 GEMM body: 3-stage cp.async pipeline, atomic epilogue --------
__device__ __forceinline__ void gemm_body(const float* __restrict__ A,
                                          const float* __restrict__ W,
                                          float* __restrict__ C,
                                          int N, int n0, int k0, int kLen)
{
    __shared__ __align__(16) float As[3][32][36];
    __shared__ __align__(16) float Ws[3][64][36];

    const int tid  = threadIdx.x;
    const int lane = tid & 31;
    const int wid  = tid >> 5;

    auto load_tile = [&](int kt, int buf) {
#pragma unroll
        for (int i = 0; i < 2; i++) {
            int ch = tid + i * 128;
            int row = ch >> 3, kc = (ch & 7) * 4;
            unsigned dst = (unsigned)__cvta_generic_to_shared(&As[buf][row][kc]);
            asm volatile("cp.async.cg.shared.global [%0], [%1], 16;"
                         :: "r"(dst), "l"(A + (long)row * 4096 + kt + kc));
        }
#pragma unroll
        for (int i = 0; i < 4; i++) {
            int ch = tid + i * 128;
            int row = ch >> 3, kc = (ch & 7) * 4;
            unsigned dst = (unsigned)__cvta_generic_to_shared(&Ws[buf][row][kc]);
            asm volatile("cp.async.cg.shared.global [%0], [%1], 16;"
                         :: "r"(dst), "l"(W + (long)(n0 + row) * 4096 + kt + kc));
        }
    };

    float c[2][2][4];
#pragma unroll
    for (int mt = 0; mt < 2; mt++)
#pragma unroll
        for (int nt = 0; nt < 2; nt++)
#pragma unroll
            for (int j = 0; j < 4; j++) c[mt][nt][j] = 0.f;

    const int nIter = kLen / 32;

    load_tile(k0, 0);
    asm volatile("cp.async.commit_group;" ::: "memory");
    load_tile(k0 + 32, 1);
    asm volatile("cp.async.commit_group;" ::: "memory");
    asm volatile("cp.async.wait_group 1;" ::: "memory");
    __syncthreads();

    const int r = lane >> 2;
    const int q = lane & 3;

    for (int it = 0; it < nIter; it++) {
        const int buf = it % 3;

        if (it + 2 < nIter) load_tile(k0 + (it + 2) * 32, (it + 2) % 3);
        asm volatile("cp.async.commit_group;" ::: "memory");

#pragma unroll
        for (int k8 = 0; k8 < 4; k8++) {
            const int kk = k8 * 8 + q;
            unsigned a[2][4], b[2][2];
#pragma unroll
            for (int mt = 0; mt < 2; mt++) {
                a[mt][0] = f2tf32(As[buf][mt * 16 + r][kk]);
                a[mt][1] = f2tf32(As[buf][mt * 16 + r + 8][kk]);
                a[mt][2] = f2tf32(As[buf][mt * 16 + r][kk + 4]);
                a[mt][3] = f2tf32(As[buf][mt * 16 + r + 8][kk + 4]);
            }
#pragma unroll
            for (int nt = 0; nt < 2; nt++) {
                const int col = wid * 16 + nt * 8 + r;
                b[nt][0] = f2tf32(Ws[buf][col][kk]);
                b[nt][1] = f2tf32(Ws[buf][col][kk + 4]);
            }
#pragma unroll
            for (int mt = 0; mt < 2; mt++)
#pragma unroll
                for (int nt = 0; nt < 2; nt++)
                    mma_tf32(c[mt][nt], a[mt], b[nt]);
        }

        asm volatile("cp.async.wait_group 1;" ::: "memory");
        __syncthreads();
    }

#pragma unroll
    for (int mt = 0; mt < 2; mt++)
#pragma unroll
        for (int nt = 0; nt < 2; nt++) {
            const int row = mt * 16 + r;
            const int col = n0 + wid * 16 + nt * 8 + q * 2;
            atomicAdd(&C[(long)row * N + col],           c[mt][nt][0]);
            atomicAdd(&C[(long)row * N + col + 1],       c[mt][nt][1]);
            atomicAdd(&C[(long)(row + 8) * N + col],     c[mt][nt][2]);
            atomicAdd(&C[(long)(row + 8) * N + col + 1], c[mt][nt][3]);
        }
}

// ---------------- kernel 1: fused QKV projection ------------------------------------
__global__ void __launch_bounds__(128) qkv_gemm(const float* __restrict__ x,
                                                const float* __restrict__ wq,
                                                const float* __restrict__ wk,
                                                const float* __restrict__ wv)
{
    const int bx = blockIdx.x;
    const int sp = blockIdx.y;
    const int k0 = sp * (4096 / SPLIT);
    const int kl = 4096 / SPLIT;
    if (bx < 64) {
        gemm_body(x, wq, g_q, NHHD, bx * 64, k0, kl);
    } else if (bx < 80) {
        gemm_body(x, wk, g_k, KVD, (bx - 64) * 64, k0, kl);
    } else {
        gemm_body(x, wv, g_v, KVD, (bx - 80) * 64, k0, kl);
    }
}

// ---------------- kernel 2: in-place RoPE (+ q scaling) -----------------------------
__global__ void __launch_bounds__(256) rope_kernel(const float* __restrict__ angles)
{
    const int idx = blockIdx.x * 256 + threadIdx.x;
    const int QP = MM * NH * 64;
    const int KP = MM * NKV * 64;
    if (idx < QP) {
        int m = idx >> 11;
        int j = idx & 63;
        int off = m * NHHD + ((idx >> 6) & 31) * HD + 2 * j;
        float xr = g_q[off], xi = g_q[off + 1];
        float a = angles[m * 64 + j];
        float c, sn; sincosf(a, &sn, &c);
        g_q[off]     = (xr * c - xi * sn) * QK_SCALE;
        g_q[off + 1] = (xr * sn + xi * c) * QK_SCALE;
    } else if (idx < QP + KP) {
        int p = idx - QP;
        int m = p >> 9;
        int j = p & 63;
        int off = m * KVD + ((p >> 6) & 7) * HD + 2 * j;
        float xr = g_k[off], xi = g_k[off + 1];
        float a = angles[m * 64 + j];
        float c, sn; sincosf(a, &sn, &c);
        g_k[off]     = xr * c - xi * sn;
        g_k[off + 1] = xr * sn + xi * c;
    }
}

// ---------------- kernel 3: warp-streaming attention (R10 form, frozen) -------------
__global__ void __launch_bounds__(128, 7) attn_warp(const float* __restrict__ cache_k,
                                                    const float* __restrict__ cache_v,
                                                    const float* __restrict__ mask,
                                                    const int* __restrict__ start_pos,
                                                    const int* __restrict__ layer_idx)
{
    const int wg   = blockIdx.x * 4 + (threadIdx.x >> 5);  // 0..8191
    const int lane = threadIdx.x & 31;
    const int bh = wg >> 5;
    const int ch = wg & 31;
    const int b  = bh >> 5;
    const int h  = bh & 31;
    const int li = layer_idx[0];
    const int sp = start_pos[b];
    const int cls = lane & 3;

    float q[4][4];
#pragma unroll
    for (int s = 0; s < 4; s++) {
        float4 t = *(const float4*)(g_q + (long)(b * SS + s) * NHHD + h * HD + lane * 4);
        q[s][0] = t.x; q[s][1] = t.y; q[s][2] = t.z; q[s][3] = t.w;
    }

    unsigned long long accp[4][2];
#pragma unroll
    for (int s = 0; s < 4; s++) { accp[s][0] = 0ull; accp[s][1] = 0ull; }
    float lcur = 0.f;

    const long base = (long)b * TT * LL * NHHD + (long)li * NHHD + (long)h * HD;
    const float* mrow = mask + (long)cls * TT;
    const int t_lo = ch * CHT;

    auto finish_token = [&](float x, const float4& v4, int t, float sign) {
        float p = sign * __expf(x + mrow[t]);
        lcur += p;
        unsigned long long v01 = pack2(v4.x, v4.y);
        unsigned long long v23 = pack2(v4.z, v4.w);
#pragma unroll
        for (int s = 0; s < 4; s++) {
            float ps = __shfl_sync(0xffffffffu, p, s);
            unsigned long long pp = pack2(ps, ps);
            fma2(accp[s][0], pp, v01);
            fma2(accp[s][1], pp, v23);
        }
    };

    auto do_token = [&](const float4& k4, const float4& v4, int t, float sign) {
        float dot[4];
#pragma unroll
        for (int s = 0; s < 4; s++) {
            float a = q[s][0] * k4.x;
            a = fmaf(q[s][1], k4.y, a);
            a = fmaf(q[s][2], k4.z, a);
            a = fmaf(q[s][3], k4.w, a);
            dot[s] = a;
        }
#pragma unroll
        for (int o = 1; o <= 2; o <<= 1)
#pragma unroll
            for (int s = 0; s < 4; s++)
                dot[s] += __shfl_xor_sync(0xffffffffu, dot[s], o);
        float x = (cls == 0) ? dot[0] : (cls == 1) ? dot[1]
                : (cls == 2) ? dot[2] : dot[3];
        x += __shfl_xor_sync(0xffffffffu, x, 4);
        x += __shfl_xor_sync(0xffffffffu, x, 8);
        x += __shfl_xor_sync(0xffffffffu, x, 16);
        finish_token(x, v4, t, sign);
    };

    const float* kptr = cache_k + base + lane * 4 + (long)t_lo * LL * NHHD;
    const float* vptr = cache_v + base + lane * 4 + (long)t_lo * LL * NHHD;
    for (int t0 = t_lo; t0 < t_lo + CHT; t0 += 2) {
        float4 k4a = *(const float4*)kptr;
        float4 v4a = *(const float4*)vptr;
        float4 k4b = *(const float4*)(kptr + LL * NHHD);
        float4 v4b = *(const float4*)(vptr + LL * NHHD);
        kptr += 2 * LL * NHHD;
        vptr += 2 * LL * NHHD;

        float dot[2][4];
#pragma unroll
        for (int s = 0; s < 4; s++) {
            float a0 = q[s][0] * k4a.x;
            a0 = fmaf(q[s][1], k4a.y, a0);
            a0 = fmaf(q[s][2], k4a.z, a0);
            a0 = fmaf(q[s][3], k4a.w, a0);
            dot[0][s] = a0;
            float a1 = q[s][0] * k4b.x;
            a1 = fmaf(q[s][1], k4b.y, a1);
            a1 = fmaf(q[s][2], k4b.z, a1);
            a1 = fmaf(q[s][3], k4b.w, a1);
            dot[1][s] = a1;
        }

#pragma unroll
        for (int o = 1; o <= 2; o <<= 1)
#pragma unroll
            for (int i = 0; i < 2; i++)
#pragma unroll
                for (int s = 0; s < 4; s++)
                    dot[i][s] += __shfl_xor_sync(0xffffffffu, dot[i][s], o);

        float xa = (cls == 0) ? dot[0][0] : (cls == 1) ? dot[0][1]
                 : (cls == 2) ? dot[0][2] : dot[0][3];
        float xb = (cls == 0) ? dot[1][0] : (cls == 1) ? dot[1][1]
                 : (cls == 2) ? dot[1][2] : dot[1][3];
#pragma unroll
        for (int o = 4; o <= 16; o <<= 1) {
            xa += __shfl_xor_sync(0xffffffffu, xa, o);
            xb += __shfl_xor_sync(0xffffffffu, xb, o);
        }

        finish_token(xa, v4a, t0,     1.f);
        finish_token(xb, v4b, t0 + 1, 1.f);
    }

    // fixup: overridden rows [sp, sp+SS) within this chunk
    {
        int lo = t_lo > sp ? t_lo : sp;
        int hi_ = t_lo + CHT < sp + SS ? t_lo + CHT : sp + SS;
        const int kvh = h >> 2;
        for (int t = lo; t < hi_; ++t) {
            float4 kc = *(const float4*)(cache_k + base + (long)t * LL * NHHD + lane * 4);
            float4 vc = *(const float4*)(cache_v + base + (long)t * LL * NHHD + lane * 4);
            do_token(kc, vc, t, -1.f);
            long noff = ((long)((b * SS + (t - sp)) * NKV + kvh)) * HD + lane * 4;
            float4 kn = *(const float4*)(g_k + noff);
            float4 vn = *(const float4*)(g_v + noff);
            do_token(kn, vn, t, 1.f);
        }
    }

    const long pbase = ((long)(bh * NCH + ch)) * SS;
#pragma unroll
    for (int s = 0; s < 4; s++) {
        float4 o;
        unpack2(accp[s][0], o.x, o.y);
        unpack2(accp[s][1], o.z, o.w);
        *(float4*)(g_pa + (pbase + s) * HD + lane * 4) = o;
    }
    if (lane < 4) g_pl[pbase + lane] = lcur;
}

// ---------------- kernel 3b: combine split-T partials -------------------------------
__global__ void __launch_bounds__(256) attn_combine()
{
    const int idx = blockIdx.x * 256 + threadIdx.x;
    const int bh = idx >> 9;
    const int s  = (idx >> 7) & 3;
    const int d  = idx & 127;
    const int b  = bh >> 5;
    const int h  = bh & 31;

    float num = 0.f, den = 0.f;
#pragma unroll
    for (int c = 0; c < NCH; c++) {
        long pb = ((long)(bh * NCH + c)) * SS + s;
        num += g_pa[pb * HD + d];
        den += g_pl[pb];
    }
    g_attn[(long)(b * SS + s) * NHHD + h * HD + d] = num / den;
}

// ---------------- kernel 4: output projection (accumulates into out) ----------------
__global__ void __launch_bounds__(128) out_gemm(const float* __restrict__ wo,
                                                float* __restrict__ out)
{
    gemm_body(g_attn, wo, out, DIM,
              blockIdx.x * 64, blockIdx.y * (4096 / SPLIT), 4096 / SPLIT);
}

// ---------------- launch -------------------------------------------------------------
extern "C" void kernel_launch(void* const* d_in, const int* in_sizes, int n_in,
                              void* d_out, int out_size)
{
    const float* x         = (const float*)d_in[0];
    const int*   start_pos = (const int*)  d_in[1];
    const float* angles    = (const float*)d_in[2];
    const float* cache_k   = (const float*)d_in[3];
    const float* cache_v   = (const float*)d_in[4];
    const float* mask      = (const float*)d_in[5];
    const float* wq        = (const float*)d_in[6];
    const float* wk        = (const float*)d_in[7];
    const float* wv        = (const float*)d_in[8];
    const float* wo        = (const float*)d_in[9];
    const int*   layer_idx = (const int*)  d_in[10];
    float* out = (float*)d_out;

    zero_q<<<512, 256>>>();                                        // launch 1
    zero_kv<<<128, 256>>>();                                       // launch 2
    zero_out<<<512, 256>>>(out);                                   // launch 3
    qkv_gemm<<<dim3(96, SPLIT), 128>>>(x, wq, wk, wv);             // launch 4 (profiled)
    rope_kernel<<<320, 256>>>(angles);                             // launch 5
    attn_warp<<<2048, 128>>>(cache_k, cache_v, mask,               // launch 6
                             start_pos, layer_idx);
    attn_combine<<<512, 256>>>();                                  // launch 7
    out_gemm<<<dim3(64, SPLIT), 128>>>(wo, out);                   // launch 8
}

// round 14
// speedup vs baseline: 1.1365x; 1.0094x over previous
#include <cuda_runtime.h>
#include <math.h>

// Problem constants
#define BB   8
#define SS   4
#define TT   2048
#define LL   2
#define NH   32
#define NKV  8
#define HD   128
#define DIM  4096
#define NHHD 4096     // NH*HD
#define KVD  1024     // NKV*HD
#define MM   32       // B*S
#define SPLIT 16
#define NCH  32       // attention T-dim chunks
#define CHT  (TT/NCH) // 64 tokens per chunk
#define QK_SCALE 0.08838834764831845f  // 1/sqrt(128)

// ---------------- scratch (device globals; no allocations allowed) ----------------
__device__ float g_q[MM * NHHD];
__device__ float g_k[MM * KVD];
__device__ float g_v[MM * KVD];
__device__ float g_attn[MM * NHHD];
__device__ float g_pl[BB * NH * NCH * SS];
__device__ float g_pa[BB * NH * NCH * SS * HD];

// ---------------- tf32 / f32x2 helpers ----------------------------------------------
__device__ __forceinline__ unsigned f2tf32(float x) {
    unsigned r;
    asm("cvt.rna.tf32.f32 %0, %1;" : "=r"(r) : "f"(x));
    return r;
}

__device__ __forceinline__ void mma_tf32(float c[4], const unsigned a[4], const unsigned b[2]) {
    asm volatile("mma.sync.aligned.m16n8k8.row.col.f32.tf32.tf32.f32 "
                 "{%0,%1,%2,%3}, {%4,%5,%6,%7}, {%8,%9}, {%0,%1,%2,%3};"
                 : "+f"(c[0]), "+f"(c[1]), "+f"(c[2]), "+f"(c[3])
                 : "r"(a[0]), "r"(a[1]), "r"(a[2]), "r"(a[3]),
                   "r"(b[0]), "r"(b[1]));
}

__device__ __forceinline__ unsigned long long pack2(float lo, float hi) {
    unsigned long long r;
    asm("mov.b64 %0, {%1, %2};" : "=l"(r) : "f"(lo), "f"(hi));
    return r;
}
__device__ __forceinline__ void fma2(unsigned long long& d,
                                     unsigned long long a, unsigned long long b) {
    asm("fma.rn.f32x2 %0, %1, %2, %0;" : "+l"(d) : "l"(a), "l"(b));
}
__device__ __forceinline__ void unpack2(unsigned long long v, float& lo, float& hi) {
    asm("mov.b64 {%0, %1}, %2;" : "=f"(lo), "=f"(hi) : "l"(v));
}

// ---------------- kernels 0a/0b/0c: zero accumulation targets ------------------------
// Three tiny kernels keep qkv_gemm in the profiled 4th slot while zero-filling
// every atomicAdd target (graph replays reuse state, so re-zero every call).
__global__ void __launch_bounds__(256) zero_q()
{
    const int idx = blockIdx.x * 256 + threadIdx.x;
    g_q[idx] = 0.f;
}
__global__ void __launch_bounds__(256) zero_kv()
{
    const int idx = blockIdx.x * 256 + threadIdx.x;
    g_k[idx] = 0.f; g_v[idx] = 0.f;
}
__global__ void __launch_bounds__(256) zero_out(float* __restrict__ out)
{
    const int idx = blockIdx.x * 256 + threadIdx.x;
    out[idx] = 0.f;
}

// ---------------- tf32 GEMM body: 2-stage cp.async pipeline, atomic epilogue --------
// C[32 x N] += A[32 x 4096] * W[N x 4096]^T on the k0..k0+kLen slice.
// 2 stages x 13.8 KB = 27.6 KB smem -> 8 blocks/SM (32 warps), vs 3-stage's 5.
// Per iter: wait_group 1 (stage it ready, it+1 in flight) -> compute(it) ->
// sync -> load it+2 into the buffer just freed -> commit. The next tile's load
// is always in flight under the current tile's compute; 8 interleaved blocks
// per SM cover DRAM latency. Smem stride 36: cp.async dst 16B-aligned, scalar
// fragment LDS conflict-free (36 mod 32 = 4).
__device__ __forceinline__ void gemm_body(const float* __restrict__ A,
                                          const float* __restrict__ W,
                                          float* __restrict__ C,
                                          int N, int n0, int k0, int kLen)
{
    __shared__ __align__(16) float As[2][32][36];
    __shared__ __align__(16) float Ws[2][64][36];

    const int tid  = threadIdx.x;
    const int lane = tid & 31;
    const int wid  = tid >> 5;

    auto load_tile = [&](int kt, int buf) {
#pragma unroll
        for (int i = 0; i < 2; i++) {
            int ch = tid + i * 128;
            int row = ch >> 3, kc = (ch & 7) * 4;
            unsigned dst = (unsigned)__cvta_generic_to_shared(&As[buf][row][kc]);
            asm volatile("cp.async.cg.shared.global [%0], [%1], 16;"
                         :: "r"(dst), "l"(A + (long)row * 4096 + kt + kc));
        }
#pragma unroll
        for (int i = 0; i < 4; i++) {
            int ch = tid + i * 128;
            int row = ch >> 3, kc = (ch & 7) * 4;
            unsigned dst = (unsigned)__cvta_generic_to_shared(&Ws[buf][row][kc]);
            asm volatile("cp.async.cg.shared.global [%0], [%1], 16;"
                         :: "r"(dst), "l"(W + (long)(n0 + row) * 4096 + kt + kc));
        }
    };

    float c[2][2][4];
#pragma unroll
    for (int mt = 0; mt < 2; mt++)
#pragma unroll
        for (int nt = 0; nt < 2; nt++)
#pragma unroll
            for (int j = 0; j < 4; j++) c[mt][nt][j] = 0.f;

    const int nIter = kLen / 32;

    // prologue: stages 0 and 1 in flight
    load_tile(k0, 0);
    asm volatile("cp.async.commit_group;" ::: "memory");
    load_tile(k0 + 32, 1);
    asm volatile("cp.async.commit_group;" ::: "memory");

    const int r = lane >> 2;
    const int q = lane & 3;

    for (int it = 0; it < nIter; it++) {
        const int buf = it & 1;

        // stage it ready (leaves the it+1 group in flight)
        asm volatile("cp.async.wait_group 1;" ::: "memory");
        __syncthreads();

        // compute on stage it
#pragma unroll
        for (int k8 = 0; k8 < 4; k8++) {
            const int kk = k8 * 8 + q;
            unsigned a[2][4], b[2][2];
#pragma unroll
            for (int mt = 0; mt < 2; mt++) {
                a[mt][0] = f2tf32(As[buf][mt * 16 + r][kk]);
                a[mt][1] = f2tf32(As[buf][mt * 16 + r + 8][kk]);
                a[mt][2] = f2tf32(As[buf][mt * 16 + r][kk + 4]);
                a[mt][3] = f2tf32(As[buf][mt * 16 + r + 8][kk + 4]);
            }
#pragma unroll
            for (int nt = 0; nt < 2; nt++) {
                const int col = wid * 16 + nt * 8 + r;
                b[nt][0] = f2tf32(Ws[buf][col][kk]);
                b[nt][1] = f2tf32(Ws[buf][col][kk + 4]);
            }
#pragma unroll
            for (int mt = 0; mt < 2; mt++)
#pragma unroll
                for (int nt = 0; nt < 2; nt++)
                    mma_tf32(c[mt][nt], a[mt], b[nt]);
        }

        // all warps done reading buf -> refill it with tile it+2
        __syncthreads();
        if (it + 2 < nIter) {
            load_tile(k0 + (it + 2) * 32, buf);
            asm volatile("cp.async.commit_group;" ::: "memory");
        } else {
            // keep group count in sync for the wait_group 1 above
            asm volatile("cp.async.commit_group;" ::: "memory");
        }
    }

    // split-K accumulation straight into C via REDG
#pragma unroll
    for (int mt = 0; mt < 2; mt++)
#pragma unroll
        for (int nt = 0; nt < 2; nt++) {
            const int row = mt * 16 + r;
            const int col = n0 + wid * 16 + nt * 8 + q * 2;
            atomicAdd(&C[(long)row * N + col],           c[mt][nt][0]);
            atomicAdd(&C[(long)row * N + col + 1],       c[mt][nt][1]);
            atomicAdd(&C[(long)(row + 8) * N + col],     c[mt][nt][2]);
            atomicAdd(&C[(long)(row + 8) * N + col + 1], c[mt][nt][3]);
        }
}

// ---------------- kernel 1: fused QKV projection ------------------------------------
__global__ void __launch_bounds__(128) qkv_gemm(const float* __restrict__ x,
                                                const float* __restrict__ wq,
                                                const float* __restrict__ wk,
                                                const float* __restrict__ wv)
{
    const int bx = blockIdx.x;
    const int sp = blockIdx.y;
    const int k0 = sp * (4096 / SPLIT);
    const int kl = 4096 / SPLIT;
    if (bx < 64) {
        gemm_body(x, wq, g_q, NHHD, bx * 64, k0, kl);
    } else if (bx < 80) {
        gemm_body(x, wk, g_k, KVD, (bx - 64) * 64, k0, kl);
    } else {
        gemm_body(x, wv, g_v, KVD, (bx - 80) * 64, k0, kl);
    }
}

// ---------------- kernel 2: in-place RoPE (+ q scaling) -----------------------------
__global__ void __launch_bounds__(256) rope_kernel(const float* __restrict__ angles)
{
    const int idx = blockIdx.x * 256 + threadIdx.x;
    const int QP = MM * NH * 64;
    const int KP = MM * NKV * 64;
    if (idx < QP) {
        int m = idx >> 11;
        int j = idx & 63;
        int off = m * NHHD + ((idx >> 6) & 31) * HD + 2 * j;
        float xr = g_q[off], xi = g_q[off + 1];
        float a = angles[m * 64 + j];
        float c, sn; sincosf(a, &sn, &c);
        g_q[off]     = (xr * c - xi * sn) * QK_SCALE;
        g_q[off + 1] = (xr * sn + xi * c) * QK_SCALE;
    } else if (idx < QP + KP) {
        int p = idx - QP;
        int m = p >> 9;
        int j = p & 63;
        int off = m * KVD + ((p >> 6) & 7) * HD + 2 * j;
        float xr = g_k[off], xi = g_k[off + 1];
        float a = angles[m * 64 + j];
        float c, sn; sincosf(a, &sn, &c);
        g_k[off]     = xr * c - xi * sn;
        g_k[off + 1] = xr * sn + xi * c;
    }
}

// ---------------- kernel 3: warp-streaming attention (frozen) -----------------------
__global__ void __launch_bounds__(128, 7) attn_warp(const float* __restrict__ cache_k,
                                                    const float* __restrict__ cache_v,
                                                    const float* __restrict__ mask,
                                                    const int* __restrict__ start_pos,
                                                    const int* __restrict__ layer_idx)
{
    const int wg   = blockIdx.x * 4 + (threadIdx.x >> 5);  // 0..8191
    const int lane = threadIdx.x & 31;
    const int bh = wg >> 5;
    const int ch = wg & 31;
    const int b  = bh >> 5;
    const int h  = bh & 31;
    const int li = layer_idx[0];
    const int sp = start_pos[b];
    const int cls = lane & 3;

    float q[4][4];
#pragma unroll
    for (int s = 0; s < 4; s++) {
        float4 t = *(const float4*)(g_q + (long)(b * SS + s) * NHHD + h * HD + lane * 4);
        q[s][0] = t.x; q[s][1] = t.y; q[s][2] = t.z; q[s][3] = t.w;
    }

    unsigned long long accp[4][2];
#pragma unroll
    for (int s = 0; s < 4; s++) { accp[s][0] = 0ull; accp[s][1] = 0ull; }
    float lcur = 0.f;

    const long base = (long)b * TT * LL * NHHD + (long)li * NHHD + (long)h * HD;
    const float* mrow = mask + (long)cls * TT;
    const int t_lo = ch * CHT;

    auto finish_token = [&](float x, const float4& v4, int t, float sign) {
        float p = sign * __expf(x + mrow[t]);
        lcur += p;
        unsigned long long v01 = pack2(v4.x, v4.y);
        unsigned long long v23 = pack2(v4.z, v4.w);
#pragma unroll
        for (int s = 0; s < 4; s++) {
            float ps = __shfl_sync(0xffffffffu, p, s);
            unsigned long long pp = pack2(ps, ps);
            fma2(accp[s][0], pp, v01);
            fma2(accp[s][1], pp, v23);
        }
    };

    auto do_token = [&](const float4& k4, const float4& v4, int t, float sign) {
        float dot[4];
#pragma unroll
        for (int s = 0; s < 4; s++) {
            float a = q[s][0] * k4.x;
            a = fmaf(q[s][1], k4.y, a);
            a = fmaf(q[s][2], k4.z, a);
            a = fmaf(q[s][3], k4.w, a);
            dot[s] = a;
        }
#pragma unroll
        for (int o = 1; o <= 2; o <<= 1)
#pragma unroll
            for (int s = 0; s < 4; s++)
                dot[s] += __shfl_xor_sync(0xffffffffu, dot[s], o);
        float x = (cls == 0) ? dot[0] : (cls == 1) ? dot[1]
                : (cls == 2) ? dot[2] : dot[3];
        x += __shfl_xor_sync(0xffffffffu, x, 4);
        x += __shfl_xor_sync(0xffffffffu, x, 8);
        x += __shfl_xor_sync(0xffffffffu, x, 16);
        finish_token(x, v4, t, sign);
    };

    const float* kptr = cache_k + base + lane * 4 + (long)t_lo * LL * NHHD;
    const float* vptr = cache_v + base + lane * 4 + (long)t_lo * LL * NHHD;
    for (int t0 = t_lo; t0 < t_lo + CHT; t0 += 2) {
        float4 k4a = *(const float4*)kptr;
        float4 v4a = *(const float4*)vptr;
        float4 k4b = *(const float4*)(kptr + LL * NHHD);
        float4 v4b = *(const float4*)(vptr + LL * NHHD);
        kptr += 2 * LL * NHHD;
        vptr += 2 * LL * NHHD;

        float dot[2][4];
#pragma unroll
        for (int s = 0; s < 4; s++) {
            float a0 = q[s][0] * k4a.x;
            a0 = fmaf(q[s][1], k4a.y, a0);
            a0 = fmaf(q[s][2], k4a.z, a0);
            a0 = fmaf(q[s][3], k4a.w, a0);
            dot[0][s] = a0;
            float a1 = q[s][0] * k4b.x;
            a1 = fmaf(q[s][1], k4b.y, a1);
            a1 = fmaf(q[s][2], k4b.z, a1);
            a1 = fmaf(q[s][3], k4b.w, a1);
            dot[1][s] = a1;
        }

#pragma unroll
        for (int o = 1; o <= 2; o <<= 1)
#pragma unroll
            for (int i = 0; i < 2; i++)
#pragma unroll
                for (int s = 0; s < 4; s++)
                    dot[i][s] += __shfl_xor_sync(0xffffffffu, dot[i][s], o);

        float xa = (cls == 0) ? dot[0][0] : (cls == 1) ? dot[0][1]
                 : (cls == 2) ? dot[0][2] : dot[0][3];
        float xb = (cls == 0) ? dot[1][0] : (cls == 1) ? dot[1][1]
                 : (cls == 2) ? dot[1][2] : dot[1][3];
#pragma unroll
        for (int o = 4; o <= 16; o <<= 1) {
            xa += __shfl_xor_sync(0xffffffffu, xa, o);
            xb += __shfl_xor_sync(0xffffffffu, xb, o);
        }

        finish_token(xa, v4a, t0,     1.f);
        finish_token(xb, v4b, t0 + 1, 1.f);
    }

    // fixup: overridden rows [sp, sp+SS) within this chunk
    {
        int lo = t_lo > sp ? t_lo : sp;
        int hi_ = t_lo + CHT < sp + SS ? t_lo + CHT : sp + SS;
        const int kvh = h >> 2;
        for (int t = lo; t < hi_; ++t) {
            float4 kc = *(const float4*)(cache_k + base + (long)t * LL * NHHD + lane * 4);
            float4 vc = *(const float4*)(cache_v + base + (long)t * LL * NHHD + lane * 4);
            do_token(kc, vc, t, -1.f);
            long noff = ((long)((b * SS + (t - sp)) * NKV + kvh)) * HD + lane * 4;
            float4 kn = *(const float4*)(g_k + noff);
            float4 vn = *(const float4*)(g_v + noff);
            do_token(kn, vn, t, 1.f);
        }
    }

    const long pbase = ((long)(bh * NCH + ch)) * SS;
#pragma unroll
    for (int s = 0; s < 4; s++) {
        float4 o;
        unpack2(accp[s][0], o.x, o.y);
        unpack2(accp[s][1], o.z, o.w);
        *(float4*)(g_pa + (pbase + s) * HD + lane * 4) = o;
    }
    if (lane < 4) g_pl[pbase + lane] = lcur;
}

// ---------------- kernel 3b: combine split-T partials -------------------------------
__global__ void __launch_bounds__(256) attn_combine()
{
    const int idx = blockIdx.x * 256 + threadIdx.x;
    const int bh = idx >> 9;
    const int s  = (idx >> 7) & 3;
    const int d  = idx & 127;
    const int b  = bh >> 5;
    const int h  = bh & 31;

    float num = 0.f, den = 0.f;
#pragma unroll
    for (int c = 0; c < NCH; c++) {
        long pb = ((long)(bh * NCH + c)) * SS + s;
        num += g_pa[pb * HD + d];
        den += g_pl[pb];
    }
    g_attn[(long)(b * SS + s) * NHHD + h * HD + d] = num / den;
}

// ---------------- kernel 4: output projection (accumulates into out) ----------------
__global__ void __launch_bounds__(128) out_gemm(const float* __restrict__ wo,
                                                float* __restrict__ out)
{
    gemm_body(g_attn, wo, out, DIM,
              blockIdx.x * 64, blockIdx.y * (4096 / SPLIT), 4096 / SPLIT);
}

// ---------------- launch -------------------------------------------------------------
extern "C" void kernel_launch(void* const* d_in, const int* in_sizes, int n_in,
                              void* d_out, int out_size)
{
    const float* x         = (const float*)d_in[0];
    const int*   start_pos = (const int*)  d_in[1];
    const float* angles    = (const float*)d_in[2];
    const float* cache_k   = (const float*)d_in[3];
    const float* cache_v   = (const float*)d_in[4];
    const float* mask      = (const float*)d_in[5];
    const float* wq        = (const float*)d_in[6];
    const float* wk        = (const float*)d_in[7];
    const float* wv        = (const float*)d_in[8];
    const float* wo        = (const float*)d_in[9];
    const int*   layer_idx = (const int*)  d_in[10];
    float* out = (float*)d_out;

    zero_q<<<512, 256>>>();                                        // launch 1
    zero_kv<<<128, 256>>>();                                       // launch 2
    zero_out<<<512, 256>>>(out);                                   // launch 3
    qkv_gemm<<<dim3(96, SPLIT), 128>>>(x, wq, wk, wv);             // launch 4 (profiled)
    rope_kernel<<<320, 256>>>(angles);                             // launch 5
    attn_warp<<<2048, 128>>>(cache_k, cache_v, mask,               // launch 6
                             start_pos, layer_idx);
    attn_combine<<<512, 256>>>();                                  // launch 7
    out_gemm<<<dim3(64, SPLIT), 128>>>(wo, out);                   // launch 8
}

// round 16
// speedup vs baseline: 1.1520x; 1.0136x over previous
#include <cuda_runtime.h>
#include <math.h>

// Problem constants
#define BB   8
#define SS   4
#define TT   2048
#define LL   2
#define NH   32
#define NKV  8
#define HD   128
#define DIM  4096
#define NHHD 4096     // NH*HD
#define KVD  1024     // NKV*HD
#define MM   32       // B*S
#define SPLIT 16
#define NCH  32       // attention T-dim chunks
#define CHT  (TT/NCH) // 64 tokens per chunk
#define QK_SCALE 0.08838834764831845f  // 1/sqrt(128)

// ---------------- scratch (device globals; no allocations allowed) ----------------
__device__ float g_q[MM * NHHD];
__device__ float g_k[MM * KVD];
__device__ float g_v[MM * KVD];
__device__ float g_attn[MM * NHHD];
__device__ float g_pl[BB * NH * NCH * SS];
__device__ float g_pa[BB * NH * NCH * SS * HD];

// ---------------- tf32 / f32x2 helpers ----------------------------------------------
// NOTE (R15 negative result): raw-bit reinterpret (RZ truncation) accumulates
// bias over K=4096 and fails the 1e-3 gate (measured 2.24e-3). cvt.rna is load-
// bearing for correctness; do not remove.
__device__ __forceinline__ unsigned f2tf32(float x) {
    unsigned r;
    asm("cvt.rna.tf32.f32 %0, %1;" : "=r"(r) : "f"(x));
    return r;
}

__device__ __forceinline__ void mma_tf32(float c[4], const unsigned a[4], const unsigned b[2]) {
    asm volatile("mma.sync.aligned.m16n8k8.row.col.f32.tf32.tf32.f32 "
                 "{%0,%1,%2,%3}, {%4,%5,%6,%7}, {%8,%9}, {%0,%1,%2,%3};"
                 : "+f"(c[0]), "+f"(c[1]), "+f"(c[2]), "+f"(c[3])
                 : "r"(a[0]), "r"(a[1]), "r"(a[2]), "r"(a[3]),
                   "r"(b[0]), "r"(b[1]));
}

__device__ __forceinline__ unsigned long long pack2(float lo, float hi) {
    unsigned long long r;
    asm("mov.b64 %0, {%1, %2};" : "=l"(r) : "f"(lo), "f"(hi));
    return r;
}
__device__ __forceinline__ void fma2(unsigned long long& d,
                                     unsigned long long a, unsigned long long b) {
    asm("fma.rn.f32x2 %0, %1, %2, %0;" : "+l"(d) : "l"(a), "l"(b));
}
__device__ __forceinline__ void unpack2(unsigned long long v, float& lo, float& hi) {
    asm("mov.b64 {%0, %1}, %2;" : "=f"(lo), "=f"(hi) : "l"(v));
}

// ---------------- kernel 0: zero accumulation targets -------------------------------
__global__ void __launch_bounds__(256) zero_bufs(float* __restrict__ out)
{
    const int idx = blockIdx.x * 256 + threadIdx.x;
    if (idx < MM * NHHD)  g_q[idx] = 0.f;
    if (idx < MM * KVD) { g_k[idx] = 0.f; g_v[idx] = 0.f; }
    if (idx < MM * DIM)   out[idx] = 0.f;
}

// ---------------- tf32 GEMM body: 2-stage cp.async pipeline, atomic epilogue --------
__device__ __forceinline__ void gemm_body(const float* __restrict__ A,
                                          const float* __restrict__ W,
                                          float* __restrict__ C,
                                          int N, int n0, int k0, int kLen)
{
    __shared__ __align__(16) float As[2][32][36];
    __shared__ __align__(16) float Ws[2][64][36];

    const int tid  = threadIdx.x;
    const int lane = tid & 31;
    const int wid  = tid >> 5;

    auto load_tile = [&](int kt, int buf) {
#pragma unroll
        for (int i = 0; i < 2; i++) {
            int ch = tid + i * 128;
            int row = ch >> 3, kc = (ch & 7) * 4;
            unsigned dst = (unsigned)__cvta_generic_to_shared(&As[buf][row][kc]);
            asm volatile("cp.async.cg.shared.global [%0], [%1], 16;"
                         :: "r"(dst), "l"(A + (long)row * 4096 + kt + kc));
        }
#pragma unroll
        for (int i = 0; i < 4; i++) {
            int ch = tid + i * 128;
            int row = ch >> 3, kc = (ch & 7) * 4;
            unsigned dst = (unsigned)__cvta_generic_to_shared(&Ws[buf][row][kc]);
            asm volatile("cp.async.cg.shared.global [%0], [%1], 16;"
                         :: "r"(dst), "l"(W + (long)(n0 + row) * 4096 + kt + kc));
        }
    };

    float c[2][2][4];
#pragma unroll
    for (int mt = 0; mt < 2; mt++)
#pragma unroll
        for (int nt = 0; nt < 2; nt++)
#pragma unroll
            for (int j = 0; j < 4; j++) c[mt][nt][j] = 0.f;

    const int nIter = kLen / 32;

    load_tile(k0, 0);
    asm volatile("cp.async.commit_group;" ::: "memory");
    load_tile(k0 + 32, 1);
    asm volatile("cp.async.commit_group;" ::: "memory");

    const int r = lane >> 2;
    const int q = lane & 3;

    for (int it = 0; it < nIter; it++) {
        const int buf = it & 1;

        asm volatile("cp.async.wait_group 1;" ::: "memory");
        __syncthreads();

#pragma unroll
        for (int k8 = 0; k8 < 4; k8++) {
            const int kk = k8 * 8 + q;
            unsigned a[2][4], b[2][2];
#pragma unroll
            for (int mt = 0; mt < 2; mt++) {
                a[mt][0] = f2tf32(As[buf][mt * 16 + r][kk]);
                a[mt][1] = f2tf32(As[buf][mt * 16 + r + 8][kk]);
                a[mt][2] = f2tf32(As[buf][mt * 16 + r][kk + 4]);
                a[mt][3] = f2tf32(As[buf][mt * 16 + r + 8][kk + 4]);
            }
#pragma unroll
            for (int nt = 0; nt < 2; nt++) {
                const int col = wid * 16 + nt * 8 + r;
                b[nt][0] = f2tf32(Ws[buf][col][kk]);
                b[nt][1] = f2tf32(Ws[buf][col][kk + 4]);
            }
#pragma unroll
            for (int mt = 0; mt < 2; mt++)
#pragma unroll
                for (int nt = 0; nt < 2; nt++)
                    mma_tf32(c[mt][nt], a[mt], b[nt]);
        }

        __syncthreads();
        if (it + 2 < nIter) {
            load_tile(k0 + (it + 2) * 32, buf);
            asm volatile("cp.async.commit_group;" ::: "memory");
        } else {
            asm volatile("cp.async.commit_group;" ::: "memory");
        }
    }

#pragma unroll
    for (int mt = 0; mt < 2; mt++)
#pragma unroll
        for (int nt = 0; nt < 2; nt++) {
            const int row = mt * 16 + r;
            const int col = n0 + wid * 16 + nt * 8 + q * 2;
            atomicAdd(&C[(long)row * N + col],           c[mt][nt][0]);
            atomicAdd(&C[(long)row * N + col + 1],       c[mt][nt][1]);
            atomicAdd(&C[(long)(row + 8) * N + col],     c[mt][nt][2]);
            atomicAdd(&C[(long)(row + 8) * N + col + 1], c[mt][nt][3]);
        }
}

// ---------------- kernel 1: fused QKV projection ------------------------------------
__global__ void __launch_bounds__(128) qkv_gemm(const float* __restrict__ x,
                                                const float* __restrict__ wq,
                                                const float* __restrict__ wk,
                                                const float* __restrict__ wv)
{
    const int bx = blockIdx.x;
    const int sp = blockIdx.y;
    const int k0 = sp * (4096 / SPLIT);
    const int kl = 4096 / SPLIT;
    if (bx < 64) {
        gemm_body(x, wq, g_q, NHHD, bx * 64, k0, kl);
    } else if (bx < 80) {
        gemm_body(x, wk, g_k, KVD, (bx - 64) * 64, k0, kl);
    } else {
        gemm_body(x, wv, g_v, KVD, (bx - 80) * 64, k0, kl);
    }
}

// ---------------- kernel 2: in-place RoPE (+ q scaling) -----------------------------
__global__ void __launch_bounds__(256) rope_kernel(const float* __restrict__ angles)
{
    const int idx = blockIdx.x * 256 + threadIdx.x;
    const int QP = MM * NH * 64;
    const int KP = MM * NKV * 64;
    if (idx < QP) {
        int m = idx >> 11;
        int j = idx & 63;
        int off = m * NHHD + ((idx >> 6) & 31) * HD + 2 * j;
        float xr = g_q[off], xi = g_q[off + 1];
        float a = angles[m * 64 + j];
        float c, sn; sincosf(a, &sn, &c);
        g_q[off]     = (xr * c - xi * sn) * QK_SCALE;
        g_q[off + 1] = (xr * sn + xi * c) * QK_SCALE;
    } else if (idx < QP + KP) {
        int p = idx - QP;
        int m = p >> 9;
        int j = p & 63;
        int off = m * KVD + ((p >> 6) & 7) * HD + 2 * j;
        float xr = g_k[off], xi = g_k[off + 1];
        float a = angles[m * 64 + j];
        float c, sn; sincosf(a, &sn, &c);
        g_k[off]     = xr * c - xi * sn;
        g_k[off + 1] = xr * sn + xi * c;
    }
}

// ---------------- kernel 3: warp-streaming attention (frozen) -----------------------
__global__ void __launch_bounds__(128, 7) attn_warp(const float* __restrict__ cache_k,
                                                    const float* __restrict__ cache_v,
                                                    const float* __restrict__ mask,
                                                    const int* __restrict__ start_pos,
                                                    const int* __restrict__ layer_idx)
{
    const int wg   = blockIdx.x * 4 + (threadIdx.x >> 5);  // 0..8191
    const int lane = threadIdx.x & 31;
    const int bh = wg >> 5;
    const int ch = wg & 31;
    const int b  = bh >> 5;
    const int h  = bh & 31;
    const int li = layer_idx[0];
    const int sp = start_pos[b];
    const int cls = lane & 3;

    float q[4][4];
#pragma unroll
    for (int s = 0; s < 4; s++) {
        float4 t = *(const float4*)(g_q + (long)(b * SS + s) * NHHD + h * HD + lane * 4);
        q[s][0] = t.x; q[s][1] = t.y; q[s][2] = t.z; q[s][3] = t.w;
    }

    unsigned long long accp[4][2];
#pragma unroll
    for (int s = 0; s < 4; s++) { accp[s][0] = 0ull; accp[s][1] = 0ull; }
    float lcur = 0.f;

    const long base = (long)b * TT * LL * NHHD + (long)li * NHHD + (long)h * HD;
    const float* mrow = mask + (long)cls * TT;
    const int t_lo = ch * CHT;

    auto finish_token = [&](float x, const float4& v4, int t, float sign) {
        float p = sign * __expf(x + mrow[t]);
        lcur += p;
        unsigned long long v01 = pack2(v4.x, v4.y);
        unsigned long long v23 = pack2(v4.z, v4.w);
#pragma unroll
        for (int s = 0; s < 4; s++) {
            float ps = __shfl_sync(0xffffffffu, p, s);
            unsigned long long pp = pack2(ps, ps);
            fma2(accp[s][0], pp, v01);
            fma2(accp[s][1], pp, v23);
        }
    };

    auto do_token = [&](const float4& k4, const float4& v4, int t, float sign) {
        float dot[4];
#pragma unroll
        for (int s = 0; s < 4; s++) {
            float a = q[s][0] * k4.x;
            a = fmaf(q[s][1], k4.y, a);
            a = fmaf(q[s][2], k4.z, a);
            a = fmaf(q[s][3], k4.w, a);
            dot[s] = a;
        }
#pragma unroll
        for (int o = 1; o <= 2; o <<= 1)
#pragma unroll
            for (int s = 0; s < 4; s++)
                dot[s] += __shfl_xor_sync(0xffffffffu, dot[s], o);
        float x = (cls == 0) ? dot[0] : (cls == 1) ? dot[1]
                : (cls == 2) ? dot[2] : dot[3];
        x += __shfl_xor_sync(0xffffffffu, x, 4);
        x += __shfl_xor_sync(0xffffffffu, x, 8);
        x += __shfl_xor_sync(0xffffffffu, x, 16);
        finish_token(x, v4, t, sign);
    };

    const float* kptr = cache_k + base + lane * 4 + (long)t_lo * LL * NHHD;
    const float* vptr = cache_v + base + lane * 4 + (long)t_lo * LL * NHHD;
    for (int t0 = t_lo; t0 < t_lo + CHT; t0 += 2) {
        float4 k4a = *(const float4*)kptr;
        float4 v4a = *(const float4*)vptr;
        float4 k4b = *(const float4*)(kptr + LL * NHHD);
        float4 v4b = *(const float4*)(vptr + LL * NHHD);
        kptr += 2 * LL * NHHD;
        vptr += 2 * LL * NHHD;

        float dot[2][4];
#pragma unroll
        for (int s = 0; s < 4; s++) {
            float a0 = q[s][0] * k4a.x;
            a0 = fmaf(q[s][1], k4a.y, a0);
            a0 = fmaf(q[s][2], k4a.z, a0);
            a0 = fmaf(q[s][3], k4a.w, a0);
            dot[0][s] = a0;
            float a1 = q[s][0] * k4b.x;
            a1 = fmaf(q[s][1], k4b.y, a1);
            a1 = fmaf(q[s][2], k4b.z, a1);
            a1 = fmaf(q[s][3], k4b.w, a1);
            dot[1][s] = a1;
        }

#pragma unroll
        for (int o = 1; o <= 2; o <<= 1)
#pragma unroll
            for (int i = 0; i < 2; i++)
#pragma unroll
                for (int s = 0; s < 4; s++)
                    dot[i][s] += __shfl_xor_sync(0xffffffffu, dot[i][s], o);

        float xa = (cls == 0) ? dot[0][0] : (cls == 1) ? dot[0][1]
                 : (cls == 2) ? dot[0][2] : dot[0][3];
        float xb = (cls == 0) ? dot[1][0] : (cls == 1) ? dot[1][1]
                 : (cls == 2) ? dot[1][2] : dot[1][3];
#pragma unroll
        for (int o = 4; o <= 16; o <<= 1) {
            xa += __shfl_xor_sync(0xffffffffu, xa, o);
            xb += __shfl_xor_sync(0xffffffffu, xb, o);
        }

        finish_token(xa, v4a, t0,     1.f);
        finish_token(xb, v4b, t0 + 1, 1.f);
    }

    // fixup: overridden rows [sp, sp+SS) within this chunk
    {
        int lo = t_lo > sp ? t_lo : sp;
        int hi_ = t_lo + CHT < sp + SS ? t_lo + CHT : sp + SS;
        const int kvh = h >> 2;
        for (int t = lo; t < hi_; ++t) {
            float4 kc = *(const float4*)(cache_k + base + (long)t * LL * NHHD + lane * 4);
            float4 vc = *(const float4*)(cache_v + base + (long)t * LL * NHHD + lane * 4);
            do_token(kc, vc, t, -1.f);
            long noff = ((long)((b * SS + (t - sp)) * NKV + kvh)) * HD + lane * 4;
            float4 kn = *(const float4*)(g_k + noff);
            float4 vn = *(const float4*)(g_v + noff);
            do_token(kn, vn, t, 1.f);
        }
    }

    const long pbase = ((long)(bh * NCH + ch)) * SS;
#pragma unroll
    for (int s = 0; s < 4; s++) {
        float4 o;
        unpack2(accp[s][0], o.x, o.y);
        unpack2(accp[s][1], o.z, o.w);
        *(float4*)(g_pa + (pbase + s) * HD + lane * 4) = o;
    }
    if (lane < 4) g_pl[pbase + lane] = lcur;
}

// ---------------- kernel 3b: combine split-T partials -------------------------------
__global__ void __launch_bounds__(256) attn_combine()
{
    const int idx = blockIdx.x * 256 + threadIdx.x;
    const int bh = idx >> 9;
    const int s  = (idx >> 7) & 3;
    const int d  = idx & 127;
    const int b  = bh >> 5;
    const int h  = bh & 31;

    float num = 0.f, den = 0.f;
#pragma unroll
    for (int c = 0; c < NCH; c++) {
        long pb = ((long)(bh * NCH + c)) * SS + s;
        num += g_pa[pb * HD + d];
        den += g_pl[pb];
    }
    g_attn[(long)(b * SS + s) * NHHD + h * HD + d] = num / den;
}

// ---------------- kernel 4: output projection (accumulates into out) ----------------
__global__ void __launch_bounds__(128) out_gemm(const float* __restrict__ wo,
                                                float* __restrict__ out)
{
    gemm_body(g_attn, wo, out, DIM,
              blockIdx.x * 64, blockIdx.y * (4096 / SPLIT), 4096 / SPLIT);
}

// ---------------- launch -------------------------------------------------------------
extern "C" void kernel_launch(void* const* d_in, const int* in_sizes, int n_in,
                              void* d_out, int out_size)
{
    const float* x         = (const float*)d_in[0];
    const int*   start_pos = (const int*)  d_in[1];
    const float* angles    = (const float*)d_in[2];
    const float* cache_k   = (const float*)d_in[3];
    const float* cache_v   = (const float*)d_in[4];
    const float* mask      = (const float*)d_in[5];
    const float* wq        = (const float*)d_in[6];
    const float* wk        = (const float*)d_in[7];
    const float* wv        = (const float*)d_in[8];
    const float* wo        = (const float*)d_in[9];
    const int*   layer_idx = (const int*)  d_in[10];
    float* out = (float*)d_out;

    zero_bufs<<<512, 256>>>(out);                                  // launch 1
    qkv_gemm<<<dim3(96, SPLIT), 128>>>(x, wq, wk, wv);             // launch 2
    rope_kernel<<<320, 256>>>(angles);                             // launch 3
    attn_warp<<<2048, 128>>>(cache_k, cache_v, mask,               // launch 4 (profiled)
                             start_pos, layer_idx);
    attn_combine<<<512, 256>>>();                                  // launch 5
    out_gemm<<<dim3(64, SPLIT), 128>>>(wo, out);                   // launch 6
}